// round 2
// baseline (speedup 1.0000x reference)
#include <cuda_runtime.h>
#include <cstdint>

// Problem constants
#define B_    4096
#define LAT_  128
#define SEQ_  512
#define HID_  32
#define OUT_  64

#define ELEMS_PER_BLOCK 4           // batch elements per block (one warp pair each)
#define THREADS 256                 // 8 warps = 4 pairs

typedef unsigned long long ull;

__device__ __forceinline__ ull f2fma(ull a, ull b, ull c) {
    ull d;
    asm("fma.rn.f32x2 %0, %1, %2, %3;" : "=l"(d) : "l"(a), "l"(b), "l"(c));
    return d;
}
__device__ __forceinline__ ull f2pack(float lo, float hi) {
    ull r; asm("mov.b64 %0, {%1, %2};" : "=l"(r) : "f"(lo), "f"(hi)); return r;
}
__device__ __forceinline__ float f2sum(ull v) {
    float lo, hi; asm("mov.b64 {%0, %1}, %2;" : "=f"(lo), "=f"(hi) : "l"(v));
    return lo + hi;
}

// sigmoid / tanh via MUFU EX2 + RCP (near-fp32 accuracy)
__device__ __forceinline__ float sigf(float x) {
    float e = __expf(-x);
    return __fdividef(1.0f, 1.0f + e);
}
__device__ __forceinline__ float tanhf_fast(float x) {
    float e = __expf(-2.0f * x);
    return __fdividef(2.0f, 1.0f + e) - 1.0f;
}

#define BAR_SYNC(id)   asm volatile("bar.sync %0, 64;"   :: "r"(id) : "memory")
#define BAR_ARRIVE(id) asm volatile("bar.arrive %0, 64;" :: "r"(id) : "memory")

__global__ void __launch_bounds__(THREADS, 2)
lstm_decoder_kernel(const float* __restrict__ z,
                    const float* __restrict__ init_W,
                    const float* __restrict__ init_b,
                    const float* __restrict__ W_hh,
                    const float* __restrict__ b_ih,
                    const float* __restrict__ b_hh,
                    const float* __restrict__ out_W,
                    const float* __restrict__ out_b,
                    float* __restrict__ y)
{
    __shared__ __align__(16) float whh_s[128 * 34];            // 17408 B
    __shared__ __align__(16) float outw_s[64 * 34];            //  8704 B
    __shared__ __align__(16) float iwT_s[128 * 32];            // 16384 B
    __shared__ __align__(16) float zs[ELEMS_PER_BLOCK * 128];  //  2048 B
    __shared__ __align__(16) float hb[ELEMS_PER_BLOCK * 32];   //   512 B
    __shared__ __align__(16) float Ob[ELEMS_PER_BLOCK * 32];   //   512 B

    const int tid  = threadIdx.x;
    const int w    = tid >> 5;
    const int j    = tid & 31;
    const int e    = w >> 1;                       // element within block
    const bool roleA = ((w & 1) == 0);             // gates i,f,g + state update
    const int b    = blockIdx.x * ELEMS_PER_BLOCK + e;
    const int bid1 = 1 + 2 * e;                    // named barrier ids (1..8)
    const int bid2 = 2 + 2 * e;

    // ---- stage weights into smem (coalesced) ----
    for (int i = tid; i < 128 * 32; i += THREADS)
        whh_s[(i >> 5) * 34 + (i & 31)] = W_hh[i];
    for (int i = tid; i < 64 * 32; i += THREADS)
        outw_s[(i >> 5) * 34 + (i & 31)] = out_W[i];
    for (int i = tid; i < 32 * 128; i += THREADS) {
        int jj = i >> 7, kk = i & 127;
        iwT_s[kk * 32 + jj] = init_W[i];
    }
    for (int i = tid; i < ELEMS_PER_BLOCK * 128; i += THREADS)
        zs[i] = z[(size_t)blockIdx.x * ELEMS_PER_BLOCK * LAT_ + i];
    __syncthreads();

    // ---- per-role weight rows into registers as f32x2 pairs ----
    // roleA: chains = W_hh rows {j, 32+j, 64+j}            (gates i, f, g)
    // roleB: chains = W_hh row {96+j}, out_W rows {2j, 2j+1} (gate o, proj)
    ull W0[16], W1[16], W2[16];
    float B0, B1, B2;
    if (roleA) {
#pragma unroll
        for (int m = 0; m < 16; m++) {
            W0[m] = *reinterpret_cast<const ull*>(&whh_s[(j     ) * 34 + 2 * m]);
            W1[m] = *reinterpret_cast<const ull*>(&whh_s[(32 + j) * 34 + 2 * m]);
            W2[m] = *reinterpret_cast<const ull*>(&whh_s[(64 + j) * 34 + 2 * m]);
        }
        B0 = b_ih[j]      + b_hh[j];          // i bias
        B1 = b_ih[32 + j] + b_hh[32 + j];     // f bias
        B2 = b_ih[64 + j] + b_hh[64 + j];     // g bias
    } else {
#pragma unroll
        for (int m = 0; m < 16; m++) {
            W0[m] = *reinterpret_cast<const ull*>(&whh_s[(96 + j ) * 34 + 2 * m]);
            W1[m] = *reinterpret_cast<const ull*>(&outw_s[(2 * j    ) * 34 + 2 * m]);
            W2[m] = *reinterpret_cast<const ull*>(&outw_s[(2 * j + 1) * 34 + 2 * m]);
        }
        B0 = b_ih[96 + j] + b_hh[96 + j];     // o bias
        B1 = out_b[2 * j];
        B2 = out_b[2 * j + 1];
    }

    float* hbw = &hb[e * 32];
    float* Obw = &Ob[e * 32];

    // ---- h0 = z @ init_W^T + init_b (roleA computes, shares via smem) ----
    float h = 0.0f, c = 0.0f;
    if (roleA) {
        h = init_b[j];
        const float* zrow = &zs[e * 128];
#pragma unroll 8
        for (int k = 0; k < 128; k++)
            h = fmaf(zrow[k], iwT_s[k * 32 + j], h);
        hbw[j] = h;
    }
    __syncthreads();

    float* yo = y + (size_t)b * SEQ_ * OUT_;   // roleB advances this per store

    // ---- main recurrence ----
    for (int t = 0; t < SEQ_; t++) {
        ull a0 = f2pack(B0, 0.0f);
        ull a1 = f2pack(B1, 0.0f);
        ull a2 = f2pack(B2, 0.0f);
#pragma unroll
        for (int m = 0; m < 16; m++) {
            ull hp = *reinterpret_cast<const ull*>(&hbw[2 * m]);   // broadcast
            a0 = f2fma(W0[m], hp, a0);
            a1 = f2fma(W1[m], hp, a1);
            a2 = f2fma(W2[m], hp, a2);
        }
        if (!roleA) {
            Obw[j] = sigf(f2sum(a0));                   // sigmoided o gate
            if (t > 0) {                                 // y[t-1] = proj(h_t)
                *reinterpret_cast<ull*>(yo + 2 * j) = f2pack(f2sum(a1), f2sum(a2));
                yo += OUT_;
            }
            BAR_ARRIVE(bid1);                            // O ready, hp consumed
            BAR_SYNC(bid2);                              // wait for new h
        } else {
            BAR_SYNC(bid1);                              // wait for O / hp free
            float I = sigf(f2sum(a0));
            float F = sigf(f2sum(a1));
            float G = tanhf_fast(f2sum(a2));
            float O = Obw[j];
            c = fmaf(F, c, I * G);
            h = O * tanhf_fast(c);
            hbw[j] = h;
            BAR_ARRIVE(bid2);                            // new h published
        }
    }

    // ---- peeled final projection: y[511] = proj(h_512) (roleB) ----
    if (!roleA) {
        ull p0 = f2pack(B1, 0.0f);
        ull p1 = f2pack(B2, 0.0f);
#pragma unroll
        for (int m = 0; m < 16; m++) {
            ull hp = *reinterpret_cast<const ull*>(&hbw[2 * m]);
            p0 = f2fma(W1[m], hp, p0);
            p1 = f2fma(W2[m], hp, p1);
        }
        *reinterpret_cast<ull*>(yo + 2 * j) = f2pack(f2sum(p0), f2sum(p1));
    }
}

extern "C" void kernel_launch(void* const* d_in, const int* in_sizes, int n_in,
                              void* d_out, int out_size)
{
    // metadata order: z, init_W, init_b, W_ih, W_hh, b_ih, b_hh, out_W, out_b
    const float* z      = (const float*)d_in[0];
    const float* init_W = (const float*)d_in[1];
    const float* init_b = (const float*)d_in[2];
    // d_in[3] = W_ih: unused (input sequence is all zeros)
    const float* W_hh   = (const float*)d_in[4];
    const float* b_ih   = (const float*)d_in[5];
    const float* b_hh   = (const float*)d_in[6];
    const float* out_W  = (const float*)d_in[7];
    const float* out_b  = (const float*)d_in[8];
    float* y            = (float*)d_out;

    dim3 grid(B_ / ELEMS_PER_BLOCK);   // 1024 blocks
    dim3 block(THREADS);               // 8 warps = 4 warp pairs = 4 batch rows
    lstm_decoder_kernel<<<grid, block>>>(z, init_W, init_b, W_hh,
                                         b_ih, b_hh, out_W, out_b, y);
}